// round 2
// baseline (speedup 1.0000x reference)
#include <cuda_runtime.h>
#include <math.h>

#define BDIM 8192
#define FDIM 1024
#define EDIM 30
#define HDIM 256
#define CDIM 100
#define GDIM 4096
#define EPSV 1e-8f

#define TB 64
#define BK 16
#define NT (FDIM/BK)
#define A_STRIDE 68
#define A_TILE (BK*A_STRIDE)
#define B_TILE (BK*HDIM)
#define HS_STRIDE 260
#define HS_OFF (2*A_TILE + 2*B_TILE)
#define SMEM_FLOATS (HS_OFF + TB*HS_STRIDE)
#define MAXT 160

__device__ int   g_assign[BDIM];
__device__ int   g_counts[EDIM];
__device__ int   g_cursor[EDIM];
__device__ float g_escale[EDIM];
__device__ int   g_sorted[BDIM];
__device__ int   g_tile_expert[MAXT];
__device__ int   g_tile_start[MAXT];
__device__ int   g_tile_rows[MAXT];
__device__ int   g_ntiles;

__device__ __forceinline__ float warp_sum(float v){
  #pragma unroll
  for (int o=16;o>0;o>>=1) v += __shfl_xor_sync(0xffffffffu, v, o);
  return v;
}

// ---------------------------------------------------------------------------
// K1: per-expert routing scale  escale[e] = align[e]*capacity[e]/(||p_e||+eps)
//     also zeroes the expert histogram. One block, 30 warps (one per expert).
// ---------------------------------------------------------------------------
__global__ void prep_kernel(const float* __restrict__ protos,
                            const float* __restrict__ gnew,
                            const float* __restrict__ gmem,
                            const int*   __restrict__ class_counts){
  int warp = threadIdx.x >> 5;
  int lane = threadIdx.x & 31;
  if (threadIdx.x < EDIM) g_counts[threadIdx.x] = 0;
  if (warp >= EDIM) return;
  float d = 0.f, m2 = 0.f, n2 = 0.f;
  for (int i = lane; i < GDIM; i += 32){
    float a = gmem[(size_t)warp*GDIM + i];
    float b = gnew[i];
    d += a*b; m2 += a*a; n2 += b*b;
  }
  d = warp_sum(d); m2 = warp_sum(m2); n2 = warp_sum(n2);
  float p2 = 0.f;
  for (int f = lane; f < FDIM; f += 32){
    float p = protos[(size_t)warp*FDIM + f];
    p2 += p*p;
  }
  p2 = warp_sum(p2);
  if (lane == 0){
    float align = 0.5f*(1.0f + d/((sqrtf(m2)+EPSV)*(sqrtf(n2)+EPSV)));
    float over  = fmaxf((float)class_counts[warp]/5.0f - 1.0f, 0.0f);
    float cap   = expf(-1.5f*over);
    g_escale[warp] = align*cap/(sqrtf(p2)+EPSV);
  }
}

// ---------------------------------------------------------------------------
// K2: routing argmax. One warp per sample, x row cached in registers.
//     score[b,e] = (x_b . p_e) * escale[e]  (per-b positive scale dropped)
// ---------------------------------------------------------------------------
__global__ void route_kernel(const float* __restrict__ x,
                             const float* __restrict__ protos){
  int gw   = (int)((blockIdx.x*blockDim.x + threadIdx.x) >> 5);
  int lane = threadIdx.x & 31;
  if (gw >= BDIM) return;
  const float4* xr = (const float4*)(x + (size_t)gw*FDIM);
  float4 xv[8];
  #pragma unroll
  for (int q=0;q<8;q++) xv[q] = xr[lane + 32*q];
  float best = -3.4e38f; int bi = 0;
  for (int e=0;e<EDIM;e++){
    const float4* p = (const float4*)(protos + (size_t)e*FDIM);
    float s = 0.f;
    #pragma unroll
    for (int q=0;q<8;q++){
      float4 pv = __ldg(&p[lane + 32*q]);
      s += xv[q].x*pv.x + xv[q].y*pv.y + xv[q].z*pv.z + xv[q].w*pv.w;
    }
    s = warp_sum(s);
    s *= g_escale[e];
    if (s > best){ best = s; bi = e; }     // strict > == argmax first-index tiebreak
  }
  if (lane == 0){
    g_assign[gw] = bi;
    atomicAdd(&g_counts[bi], 1);
  }
}

// ---------------------------------------------------------------------------
// K3: prefix offsets + tile table (serial, E=30, <=157 tiles)
// ---------------------------------------------------------------------------
__global__ void plan_kernel(){
  if (threadIdx.x == 0 && blockIdx.x == 0){
    int off = 0, t = 0;
    for (int e=0;e<EDIM;e++){
      int n = g_counts[e];
      g_cursor[e] = off;
      for (int i=0;i<n;i+=TB){
        g_tile_expert[t] = e;
        g_tile_start[t]  = off + i;
        g_tile_rows[t]   = (n - i < TB) ? (n - i) : TB;
        t++;
      }
      off += n;
    }
    g_ntiles = t;
  }
}

// K4: scatter sample ids into expert-sorted order
__global__ void scatter_kernel(){
  int b = blockIdx.x*blockDim.x + threadIdx.x;
  if (b < BDIM){
    int e = g_assign[b];
    int pos = atomicAdd(&g_cursor[e], 1);
    g_sorted[pos] = b;
  }
}

// ---------------------------------------------------------------------------
// K5: per-tile  GEMM1 (64x1024 @ 1024x256) -> LN -> GELU(erf) -> GEMM2 -> out
//     256 threads, 8x8 fp32 micro-tiles, double-buffered smem.
// ---------------------------------------------------------------------------
__global__ __launch_bounds__(256, 2) void mlp_kernel(
    const float* __restrict__ x,  const float* __restrict__ W1,
    const float* __restrict__ b1, const float* __restrict__ gamma,
    const float* __restrict__ beta, const float* __restrict__ W2,
    const float* __restrict__ b2, float* __restrict__ out)
{
  if ((int)blockIdx.x >= g_ntiles) return;
  const int tile   = blockIdx.x;
  const int e      = g_tile_expert[tile];
  const int row0   = g_tile_start[tile];
  const int nvalid = g_tile_rows[tile];

  extern __shared__ float sm[];
  __shared__ int ridx[TB];

  const int t  = threadIdx.x;
  const int tx = t & 31;
  const int ty = t >> 5;

  if (t < TB){
    int li = (t < nvalid) ? (row0 + t) : row0;
    ridx[t] = g_sorted[li];
  }
  __syncthreads();

  const float* W1e = W1 + (size_t)e*FDIM*HDIM;

  const int arow = t >> 2;           // 0..63 : sample row this thread fetches
  const int akk  = (t & 3) << 2;     // k offset within BK
  const float* aptr = x + (size_t)ridx[arow]*FDIM + akk;

  int brow[4], bcol[4];
  #pragma unroll
  for (int i=0;i<4;i++){ int fid = t + 256*i; brow[i] = fid >> 6; bcol[i] = (fid & 63) << 2; }

  // prologue: load + stage k-tile 0 into buffer 0
  float4 aReg = *(const float4*)aptr;
  float4 bReg[4];
  #pragma unroll
  for (int i=0;i<4;i++) bReg[i] = *(const float4*)(W1e + (size_t)brow[i]*HDIM + bcol[i]);
  {
    float* Ad = sm;
    Ad[(akk+0)*A_STRIDE + arow] = aReg.x;
    Ad[(akk+1)*A_STRIDE + arow] = aReg.y;
    Ad[(akk+2)*A_STRIDE + arow] = aReg.z;
    Ad[(akk+3)*A_STRIDE + arow] = aReg.w;
    float* Bd = sm + 2*A_TILE;
    #pragma unroll
    for (int i=0;i<4;i++) *(float4*)&Bd[brow[i]*HDIM + bcol[i]] = bReg[i];
  }
  __syncthreads();

  float acc[8][8];
  #pragma unroll
  for (int i=0;i<8;i++)
    #pragma unroll
    for (int j=0;j<8;j++) acc[i][j] = 0.f;

  int buf = 0;
  for (int kt=0; kt<NT; ++kt){
    if (kt+1 < NT){
      aReg = *(const float4*)(aptr + (kt+1)*BK);
      const float* wb = W1e + (size_t)(kt+1)*BK*HDIM;
      #pragma unroll
      for (int i=0;i<4;i++) bReg[i] = *(const float4*)(wb + (size_t)brow[i]*HDIM + bcol[i]);
    }
    const float* Ac = sm + buf*A_TILE;
    const float* Bc = sm + 2*A_TILE + buf*B_TILE;
    #pragma unroll
    for (int kk=0; kk<BK; ++kk){
      float4 a0 = *(const float4*)&Ac[kk*A_STRIDE + 4*ty];
      float4 a1 = *(const float4*)&Ac[kk*A_STRIDE + 32 + 4*ty];
      float4 bl = *(const float4*)&Bc[kk*HDIM + 4*tx];
      float4 bh = *(const float4*)&Bc[kk*HDIM + 128 + 4*tx];
      float av[8] = {a0.x,a0.y,a0.z,a0.w,a1.x,a1.y,a1.z,a1.w};
      float bv[8] = {bl.x,bl.y,bl.z,bl.w,bh.x,bh.y,bh.z,bh.w};
      #pragma unroll
      for (int i=0;i<8;i++)
        #pragma unroll
        for (int j=0;j<8;j++)
          acc[i][j] = fmaf(av[i], bv[j], acc[i][j]);
    }
    if (kt+1 < NT){
      int nb = buf ^ 1;
      float* Ad = sm + nb*A_TILE;
      Ad[(akk+0)*A_STRIDE + arow] = aReg.x;
      Ad[(akk+1)*A_STRIDE + arow] = aReg.y;
      Ad[(akk+2)*A_STRIDE + arow] = aReg.z;
      Ad[(akk+3)*A_STRIDE + arow] = aReg.w;
      float* Bd = sm + 2*A_TILE + nb*B_TILE;
      #pragma unroll
      for (int i=0;i<4;i++) *(float4*)&Bd[brow[i]*HDIM + bcol[i]] = bReg[i];
      __syncthreads();
      buf = nb;
    }
  }

  // epilogue 1: += b1, stage h into smem
  float* hsp = sm + HS_OFF;
  {
    float4 blo = *(const float4*)&b1[e*HDIM + 4*tx];
    float4 bhi = *(const float4*)&b1[e*HDIM + 128 + 4*tx];
    float bb[8] = {blo.x,blo.y,blo.z,blo.w,bhi.x,bhi.y,bhi.z,bhi.w};
    #pragma unroll
    for (int i=0;i<8;i++){
      int r = 4*ty + (i&3) + ((i>>2)<<5);
      float4 lo = make_float4(acc[i][0]+bb[0], acc[i][1]+bb[1], acc[i][2]+bb[2], acc[i][3]+bb[3]);
      float4 hi = make_float4(acc[i][4]+bb[4], acc[i][5]+bb[5], acc[i][6]+bb[6], acc[i][7]+bb[7]);
      *(float4*)&hsp[r*HS_STRIDE + 4*tx]       = lo;
      *(float4*)&hsp[r*HS_STRIDE + 128 + 4*tx] = hi;
    }
  }
  __syncthreads();

  // LayerNorm + exact-erf GELU, warp per 8 rows
  {
    float4 glo = *(const float4*)&gamma[e*HDIM + 4*tx];
    float4 ghi = *(const float4*)&gamma[e*HDIM + 128 + 4*tx];
    float4 tlo = *(const float4*)&beta[e*HDIM + 4*tx];
    float4 thi = *(const float4*)&beta[e*HDIM + 128 + 4*tx];
    float gv[8]  = {glo.x,glo.y,glo.z,glo.w,ghi.x,ghi.y,ghi.z,ghi.w};
    float btv[8] = {tlo.x,tlo.y,tlo.z,tlo.w,thi.x,thi.y,thi.z,thi.w};
    #pragma unroll
    for (int rr=0; rr<8; ++rr){
      int r = ty*8 + rr;
      float4 v0 = *(float4*)&hsp[r*HS_STRIDE + 4*tx];
      float4 v1 = *(float4*)&hsp[r*HS_STRIDE + 128 + 4*tx];
      float vv[8] = {v0.x,v0.y,v0.z,v0.w,v1.x,v1.y,v1.z,v1.w};
      float s = 0.f, s2 = 0.f;
      #pragma unroll
      for (int k=0;k<8;k++){ s += vv[k]; s2 += vv[k]*vv[k]; }
      s = warp_sum(s); s2 = warp_sum(s2);
      float mu   = s  * (1.0f/HDIM);
      float var  = s2 * (1.0f/HDIM) - mu*mu;
      float rstd = rsqrtf(var + 1e-5f);
      #pragma unroll
      for (int k=0;k<8;k++){
        float ln = (vv[k]-mu)*rstd*gv[k] + btv[k];
        vv[k] = 0.5f*ln*(1.0f + erff(ln*0.70710678118654752f));
      }
      *(float4*)&hsp[r*HS_STRIDE + 4*tx]       = make_float4(vv[0],vv[1],vv[2],vv[3]);
      *(float4*)&hsp[r*HS_STRIDE + 128 + 4*tx] = make_float4(vv[4],vv[5],vv[6],vv[7]);
    }
  }
  __syncthreads();

  // GEMM2: [64x256] @ W2[256x100] (padded to 128 cols), K-chunked through smem
  float acc2[8][4];
  #pragma unroll
  for (int i=0;i<8;i++){ acc2[i][0]=0.f; acc2[i][1]=0.f; acc2[i][2]=0.f; acc2[i][3]=0.f; }

  float* w2s = sm;   // reuse GEMM1 A buffers (2176 floats >= 16*128)
  const float* W2e = W2 + (size_t)e*HDIM*CDIM;
  int w2r[2], w2c[2];
  #pragma unroll
  for (int i=0;i<2;i++){ int fid = t + 256*i; w2r[i] = fid >> 5; w2c[i] = (fid & 31) << 2; }

  for (int kt=0; kt<HDIM/BK; ++kt){
    __syncthreads();
    #pragma unroll
    for (int i=0;i<2;i++){
      float4 v = make_float4(0.f,0.f,0.f,0.f);
      if (w2c[i] < CDIM)
        v = *(const float4*)&W2e[(size_t)(kt*BK + w2r[i])*CDIM + w2c[i]];
      *(float4*)&w2s[w2r[i]*128 + w2c[i]] = v;
    }
    __syncthreads();
    #pragma unroll
    for (int kk=0; kk<BK; ++kk){
      float4 b = *(const float4*)&w2s[kk*128 + 4*tx];
      #pragma unroll
      for (int i=0;i<8;i++){
        int r = 4*ty + (i&3) + ((i>>2)<<5);
        float a = hsp[r*HS_STRIDE + kt*BK + kk];
        acc2[i][0] = fmaf(a, b.x, acc2[i][0]);
        acc2[i][1] = fmaf(a, b.y, acc2[i][1]);
        acc2[i][2] = fmaf(a, b.z, acc2[i][2]);
        acc2[i][3] = fmaf(a, b.w, acc2[i][3]);
      }
    }
  }

  // epilogue 2: += b2, scatter rows to their original sample slots
  if (4*tx < CDIM){   // tx <= 24 covers cols 0..99 (float4-aligned: 100e+4tx ≡ 0 mod 4)
    float4 b2v = *(const float4*)&b2[e*CDIM + 4*tx];
    #pragma unroll
    for (int i=0;i<8;i++){
      int r = 4*ty + (i&3) + ((i>>2)<<5);
      if (r < nvalid){
        int sdx = ridx[r];
        float4 o = make_float4(acc2[i][0]+b2v.x, acc2[i][1]+b2v.y,
                               acc2[i][2]+b2v.z, acc2[i][3]+b2v.w);
        *(float4*)&out[(size_t)sdx*CDIM + 4*tx] = o;
      }
    }
  }
}

// ---------------------------------------------------------------------------
extern "C" void kernel_launch(void* const* d_in, const int* in_sizes, int n_in,
                              void* d_out, int out_size){
  const float* x      = (const float*)d_in[0];
  const float* protos = (const float*)d_in[1];
  const float* gnew   = (const float*)d_in[2];
  const float* gmem   = (const float*)d_in[3];
  const int*   cc     = (const int*)  d_in[4];
  const float* W1     = (const float*)d_in[5];
  const float* b1     = (const float*)d_in[6];
  const float* gamma  = (const float*)d_in[7];
  const float* beta   = (const float*)d_in[8];
  const float* W2     = (const float*)d_in[9];
  const float* b2     = (const float*)d_in[10];
  float* out = (float*)d_out;

  prep_kernel<<<1, 960>>>(protos, gnew, gmem, cc);
  route_kernel<<<BDIM/8, 256>>>(x, protos);
  plan_kernel<<<1, 32>>>();
  scatter_kernel<<<BDIM/256, 256>>>();

  size_t smem_bytes = SMEM_FLOATS * sizeof(float);
  cudaFuncSetAttribute(mlp_kernel, cudaFuncAttributeMaxDynamicSharedMemorySize, (int)smem_bytes);
  mlp_kernel<<<MAXT, 256, smem_bytes>>>(x, W1, b1, gamma, beta, W2, b2, out);
}

// round 3
// speedup vs baseline: 1.0375x; 1.0375x over previous
#include <cuda_runtime.h>
#include <math.h>

#define BDIM 8192
#define FDIM 1024
#define EDIM 30
#define HDIM 256
#define CDIM 100
#define GDIM 4096
#define EPSV 1e-8f

#define TB 64
#define BK 16
#define NT (FDIM/BK)
#define A_STRIDE 68
#define A_TILE (BK*A_STRIDE)
#define B_TILE (BK*HDIM)
#define HS_STRIDE 260
#define HS_OFF (2*A_TILE + 2*B_TILE)
#define SMEM_FLOATS (HS_OFF + TB*HS_STRIDE)
#define MAXT 160

__device__ int   g_assign[BDIM];
__device__ int   g_counts[EDIM];
__device__ int   g_cursor[EDIM];
__device__ float g_escale[EDIM];
__device__ int   g_sorted[BDIM];
__device__ int   g_tile_expert[MAXT];
__device__ int   g_tile_start[MAXT];
__device__ int   g_tile_rows[MAXT];
__device__ int   g_ntiles;

__device__ __forceinline__ float warp_sum(float v){
  #pragma unroll
  for (int o=16;o>0;o>>=1) v += __shfl_xor_sync(0xffffffffu, v, o);
  return v;
}

// ---- packed fp32x2 helpers (sm_103a FFMA2: only reachable via PTX) ----
typedef unsigned long long u64;

__device__ __forceinline__ u64 pk(float lo, float hi){
  u64 r; asm("mov.b64 %0, {%1, %2};" : "=l"(r) : "f"(lo), "f"(hi)); return r;
}
__device__ __forceinline__ u64 pk2(float v){
  u64 r; asm("mov.b64 %0, {%1, %1};" : "=l"(r) : "f"(v)); return r;
}
__device__ __forceinline__ void upk(u64 p, float& lo, float& hi){
  asm("mov.b64 {%0, %1}, %2;" : "=f"(lo), "=f"(hi) : "l"(p));
}
__device__ __forceinline__ void ffma2(u64& d, u64 a, u64 b){
  asm("fma.rn.f32x2 %0, %1, %2, %0;" : "+l"(d) : "l"(a), "l"(b));
}

// ---------------------------------------------------------------------------
// K1: per-expert routing scale  escale[e] = align[e]*capacity[e]/(||p_e||+eps)
// ---------------------------------------------------------------------------
__global__ void prep_kernel(const float* __restrict__ protos,
                            const float* __restrict__ gnew,
                            const float* __restrict__ gmem,
                            const int*   __restrict__ class_counts){
  int warp = threadIdx.x >> 5;
  int lane = threadIdx.x & 31;
  if (threadIdx.x < EDIM) g_counts[threadIdx.x] = 0;
  if (warp >= EDIM) return;
  float d = 0.f, m2 = 0.f, n2 = 0.f;
  for (int i = lane; i < GDIM; i += 32){
    float a = gmem[(size_t)warp*GDIM + i];
    float b = gnew[i];
    d += a*b; m2 += a*a; n2 += b*b;
  }
  d = warp_sum(d); m2 = warp_sum(m2); n2 = warp_sum(n2);
  float p2 = 0.f;
  for (int f = lane; f < FDIM; f += 32){
    float p = protos[(size_t)warp*FDIM + f];
    p2 += p*p;
  }
  p2 = warp_sum(p2);
  if (lane == 0){
    float align = 0.5f*(1.0f + d/((sqrtf(m2)+EPSV)*(sqrtf(n2)+EPSV)));
    float over  = fmaxf((float)class_counts[warp]/5.0f - 1.0f, 0.0f);
    float cap   = expf(-1.5f*over);
    g_escale[warp] = align*cap/(sqrtf(p2)+EPSV);
  }
}

// ---------------------------------------------------------------------------
// K2: routing argmax. One warp per sample, x row cached in registers.
// ---------------------------------------------------------------------------
__global__ void route_kernel(const float* __restrict__ x,
                             const float* __restrict__ protos){
  int gw   = (int)((blockIdx.x*blockDim.x + threadIdx.x) >> 5);
  int lane = threadIdx.x & 31;
  if (gw >= BDIM) return;
  const float4* xr = (const float4*)(x + (size_t)gw*FDIM);
  float4 xv[8];
  #pragma unroll
  for (int q=0;q<8;q++) xv[q] = xr[lane + 32*q];
  float best = -3.4e38f; int bi = 0;
  for (int e=0;e<EDIM;e++){
    const float4* p = (const float4*)(protos + (size_t)e*FDIM);
    float s = 0.f;
    #pragma unroll
    for (int q=0;q<8;q++){
      float4 pv = __ldg(&p[lane + 32*q]);
      s += xv[q].x*pv.x + xv[q].y*pv.y + xv[q].z*pv.z + xv[q].w*pv.w;
    }
    s = warp_sum(s);
    s *= g_escale[e];
    if (s > best){ best = s; bi = e; }     // strict > == argmax first-index tiebreak
  }
  if (lane == 0){
    g_assign[gw] = bi;
    atomicAdd(&g_counts[bi], 1);
  }
}

// ---------------------------------------------------------------------------
// K3: prefix offsets + tile table (serial, E=30, <=157 tiles)
// ---------------------------------------------------------------------------
__global__ void plan_kernel(){
  if (threadIdx.x == 0 && blockIdx.x == 0){
    int off = 0, t = 0;
    for (int e=0;e<EDIM;e++){
      int n = g_counts[e];
      g_cursor[e] = off;
      for (int i=0;i<n;i+=TB){
        g_tile_expert[t] = e;
        g_tile_start[t]  = off + i;
        g_tile_rows[t]   = (n - i < TB) ? (n - i) : TB;
        t++;
      }
      off += n;
    }
    g_ntiles = t;
  }
}

// K4: scatter sample ids into expert-sorted order
__global__ void scatter_kernel(){
  int b = blockIdx.x*blockDim.x + threadIdx.x;
  if (b < BDIM){
    int e = g_assign[b];
    int pos = atomicAdd(&g_cursor[e], 1);
    g_sorted[pos] = b;
  }
}

// ---------------------------------------------------------------------------
// K5: per-tile  GEMM1 (64x1024 @ 1024x256) -> LN -> GELU(erf) -> GEMM2 -> out
//     256 threads, 8x8 micro-tiles, FFMA2 packed math, double-buffered smem.
// ---------------------------------------------------------------------------
__global__ __launch_bounds__(256, 2) void mlp_kernel(
    const float* __restrict__ x,  const float* __restrict__ W1,
    const float* __restrict__ b1, const float* __restrict__ gamma,
    const float* __restrict__ beta, const float* __restrict__ W2,
    const float* __restrict__ b2, float* __restrict__ out)
{
  if ((int)blockIdx.x >= g_ntiles) return;
  const int tile   = blockIdx.x;
  const int e      = g_tile_expert[tile];
  const int row0   = g_tile_start[tile];
  const int nvalid = g_tile_rows[tile];

  extern __shared__ float sm[];
  __shared__ int ridx[TB];

  const int t  = threadIdx.x;
  const int tx = t & 31;
  const int ty = t >> 5;

  if (t < TB){
    int li = (t < nvalid) ? (row0 + t) : row0;
    ridx[t] = g_sorted[li];
  }
  __syncthreads();

  const float* W1e = W1 + (size_t)e*FDIM*HDIM;

  const int arow = t >> 2;           // 0..63 : sample row this thread fetches
  const int akk  = (t & 3) << 2;     // k offset within BK
  const float* aptr = x + (size_t)ridx[arow]*FDIM + akk;

  int brow[4], bcol[4];
  #pragma unroll
  for (int i=0;i<4;i++){ int fid = t + 256*i; brow[i] = fid >> 6; bcol[i] = (fid & 63) << 2; }

  // prologue: load + stage k-tile 0 into buffer 0
  float4 aReg = *(const float4*)aptr;
  float4 bReg[4];
  #pragma unroll
  for (int i=0;i<4;i++) bReg[i] = *(const float4*)(W1e + (size_t)brow[i]*HDIM + bcol[i]);
  {
    float* Ad = sm;
    Ad[(akk+0)*A_STRIDE + arow] = aReg.x;
    Ad[(akk+1)*A_STRIDE + arow] = aReg.y;
    Ad[(akk+2)*A_STRIDE + arow] = aReg.z;
    Ad[(akk+3)*A_STRIDE + arow] = aReg.w;
    float* Bd = sm + 2*A_TILE;
    #pragma unroll
    for (int i=0;i<4;i++) *(float4*)&Bd[brow[i]*HDIM + bcol[i]] = bReg[i];
  }
  __syncthreads();

  // packed accumulators: accp[i][j] holds output cols pair
  //   j=0 -> (4tx+0, 4tx+1)   j=1 -> (4tx+2, 4tx+3)
  //   j=2 -> (128+4tx+0, +1)  j=3 -> (128+4tx+2, +3)
  u64 accp[8][4];
  #pragma unroll
  for (int i=0;i<8;i++)
    #pragma unroll
    for (int j=0;j<4;j++) accp[i][j] = 0ull;

  int buf = 0;
  for (int kt=0; kt<NT; ++kt){
    if (kt+1 < NT){
      aReg = *(const float4*)(aptr + (kt+1)*BK);
      const float* wb = W1e + (size_t)(kt+1)*BK*HDIM;
      #pragma unroll
      for (int i=0;i<4;i++) bReg[i] = *(const float4*)(wb + (size_t)brow[i]*HDIM + bcol[i]);
    }
    const float* Ac = sm + buf*A_TILE;
    const float* Bc = sm + 2*A_TILE + buf*B_TILE;
    #pragma unroll
    for (int kk=0; kk<BK; ++kk){
      float4 a0 = *(const float4*)&Ac[kk*A_STRIDE + 4*ty];
      float4 a1 = *(const float4*)&Ac[kk*A_STRIDE + 32 + 4*ty];
      float4 bl = *(const float4*)&Bc[kk*HDIM + 4*tx];
      float4 bh = *(const float4*)&Bc[kk*HDIM + 128 + 4*tx];
      u64 bp0 = pk(bl.x, bl.y), bp1 = pk(bl.z, bl.w);
      u64 bp2 = pk(bh.x, bh.y), bp3 = pk(bh.z, bh.w);
      float av[8] = {a0.x,a0.y,a0.z,a0.w,a1.x,a1.y,a1.z,a1.w};
      #pragma unroll
      for (int i=0;i<8;i++){
        u64 ad = pk2(av[i]);
        ffma2(accp[i][0], ad, bp0);
        ffma2(accp[i][1], ad, bp1);
        ffma2(accp[i][2], ad, bp2);
        ffma2(accp[i][3], ad, bp3);
      }
    }
    if (kt+1 < NT){
      int nb = buf ^ 1;
      float* Ad = sm + nb*A_TILE;
      Ad[(akk+0)*A_STRIDE + arow] = aReg.x;
      Ad[(akk+1)*A_STRIDE + arow] = aReg.y;
      Ad[(akk+2)*A_STRIDE + arow] = aReg.z;
      Ad[(akk+3)*A_STRIDE + arow] = aReg.w;
      float* Bd = sm + 2*A_TILE + nb*B_TILE;
      #pragma unroll
      for (int i=0;i<4;i++) *(float4*)&Bd[brow[i]*HDIM + bcol[i]] = bReg[i];
      __syncthreads();
      buf = nb;
    }
  }

  // epilogue 1: += b1, stage h into smem
  float* hsp = sm + HS_OFF;
  {
    float4 blo = *(const float4*)&b1[e*HDIM + 4*tx];
    float4 bhi = *(const float4*)&b1[e*HDIM + 128 + 4*tx];
    float bb[8] = {blo.x,blo.y,blo.z,blo.w,bhi.x,bhi.y,bhi.z,bhi.w};
    #pragma unroll
    for (int i=0;i<8;i++){
      int r = 4*ty + (i&3) + ((i>>2)<<5);
      float c0,c1,c2,c3,c4,c5,c6,c7;
      upk(accp[i][0], c0, c1); upk(accp[i][1], c2, c3);
      upk(accp[i][2], c4, c5); upk(accp[i][3], c6, c7);
      float4 lo = make_float4(c0+bb[0], c1+bb[1], c2+bb[2], c3+bb[3]);
      float4 hi = make_float4(c4+bb[4], c5+bb[5], c6+bb[6], c7+bb[7]);
      *(float4*)&hsp[r*HS_STRIDE + 4*tx]       = lo;
      *(float4*)&hsp[r*HS_STRIDE + 128 + 4*tx] = hi;
    }
  }
  __syncthreads();

  // LayerNorm + exact-erf GELU, warp per 8 rows
  {
    float4 glo = *(const float4*)&gamma[e*HDIM + 4*tx];
    float4 ghi = *(const float4*)&gamma[e*HDIM + 128 + 4*tx];
    float4 tlo = *(const float4*)&beta[e*HDIM + 4*tx];
    float4 thi = *(const float4*)&beta[e*HDIM + 128 + 4*tx];
    float gv[8]  = {glo.x,glo.y,glo.z,glo.w,ghi.x,ghi.y,ghi.z,ghi.w};
    float btv[8] = {tlo.x,tlo.y,tlo.z,tlo.w,thi.x,thi.y,thi.z,thi.w};
    #pragma unroll
    for (int rr=0; rr<8; ++rr){
      int r = ty*8 + rr;
      float4 v0 = *(float4*)&hsp[r*HS_STRIDE + 4*tx];
      float4 v1 = *(float4*)&hsp[r*HS_STRIDE + 128 + 4*tx];
      float vv[8] = {v0.x,v0.y,v0.z,v0.w,v1.x,v1.y,v1.z,v1.w};
      float s = 0.f, s2 = 0.f;
      #pragma unroll
      for (int k=0;k<8;k++){ s += vv[k]; s2 += vv[k]*vv[k]; }
      s = warp_sum(s); s2 = warp_sum(s2);
      float mu   = s  * (1.0f/HDIM);
      float var  = s2 * (1.0f/HDIM) - mu*mu;
      float rstd = rsqrtf(var + 1e-5f);
      #pragma unroll
      for (int k=0;k<8;k++){
        float ln = (vv[k]-mu)*rstd*gv[k] + btv[k];
        vv[k] = 0.5f*ln*(1.0f + erff(ln*0.70710678118654752f));
      }
      *(float4*)&hsp[r*HS_STRIDE + 4*tx]       = make_float4(vv[0],vv[1],vv[2],vv[3]);
      *(float4*)&hsp[r*HS_STRIDE + 128 + 4*tx] = make_float4(vv[4],vv[5],vv[6],vv[7]);
    }
  }
  __syncthreads();

  // GEMM2: [64x256] @ W2[256x100] (padded to 128 cols), K-chunked through smem
  u64 acc2p[8][2];
  #pragma unroll
  for (int i=0;i<8;i++){ acc2p[i][0]=0ull; acc2p[i][1]=0ull; }

  float* w2s = sm;   // reuse GEMM1 A buffers (2176 floats >= 16*128)
  const float* W2e = W2 + (size_t)e*HDIM*CDIM;
  int w2r[2], w2c[2];
  #pragma unroll
  for (int i=0;i<2;i++){ int fid = t + 256*i; w2r[i] = fid >> 5; w2c[i] = (fid & 31) << 2; }

  for (int kt=0; kt<HDIM/BK; ++kt){
    __syncthreads();
    #pragma unroll
    for (int i=0;i<2;i++){
      float4 v = make_float4(0.f,0.f,0.f,0.f);
      if (w2c[i] < CDIM)
        v = *(const float4*)&W2e[(size_t)(kt*BK + w2r[i])*CDIM + w2c[i]];
      *(float4*)&w2s[w2r[i]*128 + w2c[i]] = v;
    }
    __syncthreads();
    #pragma unroll
    for (int kq=0; kq<BK/4; ++kq){
      // vectorized A reads: 4 consecutive k values per row
      float4 ak[8];
      #pragma unroll
      for (int i=0;i<8;i++){
        int r = 4*ty + (i&3) + ((i>>2)<<5);
        ak[i] = *(const float4*)&hsp[r*HS_STRIDE + kt*BK + 4*kq];
      }
      #pragma unroll
      for (int q=0; q<4; ++q){
        int kk = 4*kq + q;
        float4 b = *(const float4*)&w2s[kk*128 + 4*tx];
        u64 b0 = pk(b.x, b.y), b1p = pk(b.z, b.w);
        #pragma unroll
        for (int i=0;i<8;i++){
          float a = (q==0)?ak[i].x:(q==1)?ak[i].y:(q==2)?ak[i].z:ak[i].w;
          u64 ad = pk2(a);
          ffma2(acc2p[i][0], ad, b0);
          ffma2(acc2p[i][1], ad, b1p);
        }
      }
    }
  }

  // epilogue 2: += b2, scatter rows to their original sample slots
  if (4*tx < CDIM){   // tx <= 24 covers cols 0..99 (float4-aligned: 100e+4tx ≡ 0 mod 4)
    float4 b2v = *(const float4*)&b2[e*CDIM + 4*tx];
    #pragma unroll
    for (int i=0;i<8;i++){
      int r = 4*ty + (i&3) + ((i>>2)<<5);
      if (r < nvalid){
        int sdx = ridx[r];
        float o0,o1,o2,o3;
        upk(acc2p[i][0], o0, o1); upk(acc2p[i][1], o2, o3);
        float4 o = make_float4(o0+b2v.x, o1+b2v.y, o2+b2v.z, o3+b2v.w);
        *(float4*)&out[(size_t)sdx*CDIM + 4*tx] = o;
      }
    }
  }
}

// ---------------------------------------------------------------------------
extern "C" void kernel_launch(void* const* d_in, const int* in_sizes, int n_in,
                              void* d_out, int out_size){
  const float* x      = (const float*)d_in[0];
  const float* protos = (const float*)d_in[1];
  const float* gnew   = (const float*)d_in[2];
  const float* gmem   = (const float*)d_in[3];
  const int*   cc     = (const int*)  d_in[4];
  const float* W1     = (const float*)d_in[5];
  const float* b1     = (const float*)d_in[6];
  const float* gamma  = (const float*)d_in[7];
  const float* beta   = (const float*)d_in[8];
  const float* W2     = (const float*)d_in[9];
  const float* b2     = (const float*)d_in[10];
  float* out = (float*)d_out;

  prep_kernel<<<1, 960>>>(protos, gnew, gmem, cc);
  route_kernel<<<BDIM/8, 256>>>(x, protos);
  plan_kernel<<<1, 32>>>();
  scatter_kernel<<<BDIM/256, 256>>>();

  size_t smem_bytes = SMEM_FLOATS * sizeof(float);
  cudaFuncSetAttribute(mlp_kernel, cudaFuncAttributeMaxDynamicSharedMemorySize, (int)smem_bytes);
  mlp_kernel<<<MAXT, 256, smem_bytes>>>(x, W1, b1, gamma, beta, W2, b2, out);
}